// round 3
// baseline (speedup 1.0000x reference)
#include <cuda_runtime.h>
#include <cstdint>

#define NCLS 21
#define NB 8
#define HW (512*512)
#define TPB 256
#define PXT 4                         // pixels per thread per iter (float4)
#define ITERS 4
#define PPB (TPB*PXT*ITERS)           // 4096 pixels per block
#define BLOCKS_PER_IMG (HW/PPB)       // 64
#define NBLK (NB*BLOCKS_PER_IMG)      // 512
#define EPS 1e-10f
#define PITCH 33                      // 32 lanes + 1 pad -> conflict-free row scans

// Per-block partials, fully overwritten every launch (no zeroing kernel needed).
__device__ float g_I [NBLK][NCLS];
__device__ float g_At[NBLK][NCLS];
__device__ float g_Ao[NBLK][NCLS];
__device__ float g_T [NBLK][NCLS];

__global__ __launch_bounds__(TPB) void hist_kernel(const float* __restrict__ pr,
                                                   const int*   __restrict__ gt) {
    // Warp-private, bank-strided accumulators: lane L only touches column L.
    __shared__ uint32_t s_cnt[8][NCLS][PITCH];   // atgt[0:10) | inter[10:20) | aout[20:30)
    __shared__ float    s_T  [8][NCLS][PITCH];
    __shared__ float    c_I[8][NCLS], c_At[8][NCLS], c_Ao[8][NCLS], c_T[8][NCLS];

    const int tid  = threadIdx.x;
    const int wid  = tid >> 5;
    const int lane = tid & 31;

    // Zero this warp's private region (693 words each)
    {
        uint32_t* pc = &s_cnt[wid][0][0];
        float*    pt = &s_T  [wid][0][0];
        #pragma unroll
        for (int r = 0; r < NCLS * PITCH; r += 32) {
            if (r + lane < NCLS * PITCH) { pc[r + lane] = 0u; pt[r + lane] = 0.f; }
        }
    }
    __syncwarp();

    const int b     = blockIdx.x / BLOCKS_PER_IMG;
    const int chunk = blockIdx.x % BLOCKS_PER_IMG;
    const float* __restrict__ base  = pr + (size_t)b * NCLS * HW;
    const int*   __restrict__ gbase = gt + (size_t)b * HW;

    #pragma unroll 1
    for (int it = 0; it < ITERS; ++it) {
        const int pix0 = chunk * PPB + it * (TPB * PXT) + tid * PXT;
        const int4 g4 = *(const int4*)(gbase + pix0);
        const float4* __restrict__ p = (const float4*)(base + pix0);

        float4 se  = make_float4(0.f, 0.f, 0.f, 0.f);
        float4 m   = make_float4(-3.0e38f, -3.0e38f, -3.0e38f, -3.0e38f);
        int4   am  = make_int4(0, 0, 0, 0);
        float4 vgt = make_float4(0.f, 0.f, 0.f, 0.f);

        #pragma unroll
        for (int k = 0; k < NCLS; ++k) {
            const float4 v = p[(size_t)k * (HW / 4)];
            se.x += __expf(v.x);  se.y += __expf(v.y);
            se.z += __expf(v.z);  se.w += __expf(v.w);
            if (v.x > m.x) { m.x = v.x; am.x = k; }   // strict >: first max wins
            if (v.y > m.y) { m.y = v.y; am.y = k; }
            if (v.z > m.z) { m.z = v.z; am.z = k; }
            if (v.w > m.w) { m.w = v.w; am.w = k; }
            if (k == g4.x) vgt.x = v.x;
            if (k == g4.y) vgt.y = v.y;
            if (k == g4.z) vgt.z = v.z;
            if (k == g4.w) vgt.w = v.w;
        }

        const float lx = vgt.x - __logf(se.x);
        const float ly = vgt.y - __logf(se.y);
        const float lz = vgt.z - __logf(se.z);
        const float lw = vgt.w - __logf(se.w);

        // Non-atomic RMW: each lane owns its column; no races, no bank conflicts.
        #define UPD(G, AM, LP) do {                                            \
            s_cnt[wid][(G)][lane]  += 1u + (((AM) == (G)) ? (1u << 10) : 0u);  \
            s_cnt[wid][(AM)][lane] += (1u << 20);                              \
            s_T  [wid][(G)][lane]  += (LP);                                    \
        } while (0)
        UPD(g4.x, am.x, lx);
        UPD(g4.y, am.y, ly);
        UPD(g4.z, am.z, lz);
        UPD(g4.w, am.w, lw);
        #undef UPD
    }
    __syncwarp();

    // Per-warp row scan: lane k (<21) sums its row's 32 columns.
    if (lane < NCLS) {
        uint32_t c = 0u; float t = 0.f;
        #pragma unroll
        for (int j = 0; j < 32; ++j) {
            c += s_cnt[wid][lane][j];
            t += s_T  [wid][lane][j];
        }
        c_At[wid][lane] = (float)( c         & 1023u);
        c_I [wid][lane] = (float)((c >> 10)  & 1023u);
        c_Ao[wid][lane] = (float)( c >> 20);
        c_T [wid][lane] = t;
    }
    __syncthreads();

    // Block combine: thread k sums 8 warps, writes per-block partials.
    if (tid < NCLS) {
        float I = 0.f, At = 0.f, Ao = 0.f, T = 0.f;
        #pragma unroll
        for (int w = 0; w < 8; ++w) {
            I += c_I[w][tid]; At += c_At[w][tid]; Ao += c_Ao[w][tid]; T += c_T[w][tid];
        }
        g_I [blockIdx.x][tid] = I;
        g_At[blockIdx.x][tid] = At;
        g_Ao[blockIdx.x][tid] = Ao;
        g_T [blockIdx.x][tid] = T;
    }
}

__global__ __launch_bounds__(192) void finalize_kernel(float* __restrict__ out) {
    __shared__ float sh_d[NB][NCLS], sh_N[NB][NCLS], sh_T[NB][NCLS];
    const int tid = threadIdx.x;

    if (tid < NB * NCLS) {
        const int bb = tid / NCLS, k = tid % NCLS;
        float I = 0.f, At = 0.f, Ao = 0.f, T = 0.f;
        #pragma unroll 8
        for (int j = 0; j < BLOCKS_PER_IMG; ++j) {
            const int blk = bb * BLOCKS_PER_IMG + j;
            I  += g_I [blk][k];
            At += g_At[blk][k];
            Ao += g_Ao[blk][k];
            T  += g_T [blk][k];
        }
        sh_d[bb][k] = 2.f * I / (Ao + At + EPS);  // union + inter == a_out + a_tgt
        sh_N[bb][k] = At;
        sh_T[bb][k] = T;
    }
    __syncthreads();

    float w = 0.f, wT = 0.f, wN = 0.f;
    if (tid < NCLS) {
        float dice = 0.f, N = 0.f, T = 0.f;
        #pragma unroll
        for (int bb = 0; bb < NB; ++bb) {
            dice += sh_d[bb][tid];
            N    += sh_N[bb][tid];
            T    += sh_T[bb][tid];
        }
        w  = 1.f - dice * 0.125f;   // weight[k]
        wT = w * T;
        wN = w * N;
    }
    if (tid < 32) {
        #pragma unroll
        for (int o = 16; o > 0; o >>= 1) {
            w  += __shfl_down_sync(0xffffffffu, w,  o);
            wT += __shfl_down_sync(0xffffffffu, wT, o);
            wN += __shfl_down_sync(0xffffffffu, wN, o);
        }
        if (tid == 0) out[0] = w * (1.f / 21.f) - wT / wN;  // mean(weight) + celoss
    }
}

extern "C" void kernel_launch(void* const* d_in, const int* in_sizes, int n_in,
                              void* d_out, int out_size) {
    const float* pr;
    const int*   gt;
    if (in_sizes[0] > in_sizes[1]) {
        pr = (const float*)d_in[0];
        gt = (const int*)  d_in[1];
    } else {
        pr = (const float*)d_in[1];
        gt = (const int*)  d_in[0];
    }
    float* out = (float*)d_out;

    hist_kernel    <<<NBLK, TPB>>>(pr, gt);
    finalize_kernel<<<1, 192>>>(out);
}